// round 11
// baseline (speedup 1.0000x reference)
#include <cuda_runtime.h>
#include <cstdint>

// SDF_75806172774865 — R11: R10 barrier-free direct-LDG + software-pipelined
// register double-buffer (prefetch next pair's loads before computing current).
// 128-thread blocks, launch_bounds(128,6) -> 24 warps/SM, loads always in flight.
// points: (N,P,3) f32 ; v,vn: (N,P,K,3) f32 ; sr: (N,P,K) f32 ; out: (N,) f32

#define K_FIX 60
#define THREADS 128
#define NWARPS 4
#define ROWF (K_FIX * 3)          // 180 floats per v/vn row
#define NMAX 8

__global__ void sdf_zero_kernel(float* __restrict__ out, int n) {
    int i = blockIdx.x * blockDim.x + threadIdx.x;
    if (i < n) out[i] = 0.0f;
}

__device__ __forceinline__ void kstep(float px, float py, float pz,
                                      float vx, float vy, float vz,
                                      float nx, float ny, float nz, float s,
                                      float& num, float& den) {
    const float dx = px - vx;
    const float dy = py - vy;
    const float dz = pz - vz;
    const float d2 = fmaf(dx, dx, fmaf(dy, dy, dz * dz));
    const float w  = 1.0f - d2 * __frcp_rn(s);
    const float w2 = w * w;
    const float phi = (d2 < s) ? (w2 * w2) : 1e-18f;
    const float dot = fmaf(nx, dx, fmaf(ny, dy, nz * dz));
    num = fmaf(phi, dot, num);
    den += phi;
}

// Issue all loads for pair pp (this thread's 4-k chunk of point gp).
#define LOAD_PAIR(S, pp_) do {                                              \
    const int gp_ = 2 * (pp_) + half;                                       \
    if (gp_ < total_points && sub < 15) {                                   \
        const float* vr_ = v      + (size_t)gp_ * ROWF  + sub * 12;         \
        const float* nr_ = vn     + (size_t)gp_ * ROWF  + sub * 12;         \
        const float* sr_ = sr     + (size_t)gp_ * K_FIX + sub * 4;          \
        const float* pr_ = points + (size_t)gp_ * 3;                        \
        va##S = __ldg((const float4*)(vr_));                                \
        vb##S = __ldg((const float4*)(vr_ + 4));                            \
        vc##S = __ldg((const float4*)(vr_ + 8));                            \
        na##S = __ldg((const float4*)(nr_));                                \
        nb##S = __ldg((const float4*)(nr_ + 4));                            \
        nc##S = __ldg((const float4*)(nr_ + 8));                            \
        s4##S = __ldg((const float4*)(sr_));                                \
        px##S = __ldg(pr_ + 0);                                             \
        py##S = __ldg(pr_ + 1);                                             \
        pz##S = __ldg(pr_ + 2);                                             \
    }                                                                       \
} while (0)

// Compute + reduce + accumulate for pair pp using register set S.
#define PROC_PAIR(S, pp_) do {                                              \
    const int gp_ = 2 * (pp_) + half;                                       \
    const bool pv_ = (gp_ < total_points);                                  \
    float num = 0.0f, den = 0.0f;                                           \
    if (pv_ && sub < 15) {                                                  \
        kstep(px##S, py##S, pz##S, va##S.x, va##S.y, va##S.z,               \
              na##S.x, na##S.y, na##S.z, s4##S.x, num, den);                \
        kstep(px##S, py##S, pz##S, va##S.w, vb##S.x, vb##S.y,               \
              na##S.w, nb##S.x, nb##S.y, s4##S.y, num, den);                \
        kstep(px##S, py##S, pz##S, vb##S.z, vb##S.w, vc##S.x,               \
              nb##S.z, nb##S.w, nc##S.x, s4##S.z, num, den);                \
        kstep(px##S, py##S, pz##S, vc##S.y, vc##S.z, vc##S.w,               \
              nc##S.y, nc##S.z, nc##S.w, s4##S.w, num, den);                \
    }                                                                       \
    _Pragma("unroll")                                                       \
    for (int o = 8; o > 0; o >>= 1) {                                       \
        num += __shfl_xor_sync(0xffffffffu, num, o);                        \
        den += __shfl_xor_sync(0xffffffffu, den, o);                        \
    }                                                                       \
    const float sdf_   = fdividef(num, den);                                \
    const float sdf2_  = pv_ ? (sdf_ * sdf_) : 0.0f;                        \
    const float sdf2B_ = __shfl_sync(0xffffffffu, sdf2_, 16);               \
    if (lane == 0) {                                                        \
        const int gpA_ = 2 * (pp_);                                         \
        if (gpA_ < total_points) {                                          \
            int niA_ = 0;                                                   \
            while (gpA_ >= (niA_ + 1) * P) niA_++;                          \
            float add_ = sdf2_;                                             \
            if (gpA_ + 1 < total_points) {                                  \
                const int niB_ = niA_ + ((gpA_ + 1) >= (niA_ + 1) * P);     \
                if (niB_ == niA_) add_ += sdf2B_;                           \
                else s_acc[warp * NMAX + niB_] += sdf2B_;                   \
            }                                                               \
            s_acc[warp * NMAX + niA_] += add_;                              \
        }                                                                   \
    }                                                                       \
} while (0)

__global__ __launch_bounds__(THREADS, 6)
void sdf_kernel(const float* __restrict__ points,
                const float* __restrict__ v,
                const float* __restrict__ vn,
                const float* __restrict__ sr,
                float* __restrict__ out,
                int total_points, int P, int N,
                int ppb_lo, int extra) {
    __shared__ float s_acc[NWARPS * NMAX];

    const int tid  = threadIdx.x;
    const int warp = tid >> 5;
    const int lane = tid & 31;
    const int half = lane >> 4;
    const int sub  = lane & 15;

    const int b_id = blockIdx.x;
    const int p0 = b_id * ppb_lo + min(b_id, extra);
    const int p1 = p0 + ppb_lo + (b_id < extra ? 1 : 0);

    if (tid < NWARPS * NMAX) s_acc[tid] = 0.0f;
    __syncthreads();

    float4 vaA, vbA, vcA, naA, nbA, ncA, s4A;
    float  pxA, pyA, pzA;
    float4 vaB, vbB, vcB, naB, nbB, ncB, s4B;
    float  pxB, pyB, pzB;

    int pp = p0 + warp;
    if (pp < p1) {
        LOAD_PAIR(A, pp);
        for (;;) {
            const int pp2 = pp + NWARPS;
            if (pp2 < p1) LOAD_PAIR(B, pp2);
            PROC_PAIR(A, pp);
            if (pp2 >= p1) break;

            const int pp3 = pp2 + NWARPS;
            if (pp3 < p1) LOAD_PAIR(A, pp3);
            PROC_PAIR(B, pp2);
            if (pp3 >= p1) break;
            pp = pp3;
        }
    }

    __syncthreads();
    if (tid < N && tid < NMAX) {
        float sum = 0.0f;
        #pragma unroll
        for (int w = 0; w < NWARPS; w++) sum += s_acc[w * NMAX + tid];
        atomicAdd(&out[tid], sum);
    }
}

extern "C" void kernel_launch(void* const* d_in, const int* in_sizes, int n_in,
                              void* d_out, int out_size) {
    const float* points = (const float*)d_in[0];
    const float* v      = (const float*)d_in[1];
    const float* vn     = (const float*)d_in[2];
    const float* sr     = (const float*)d_in[3];
    float* out = (float*)d_out;

    const int total_points = in_sizes[0] / 3;  // N*P
    const int N = out_size;
    const int P = total_points / N;

    sdf_zero_kernel<<<1, 32>>>(out, out_size);

    const int total_pairs = (total_points + 1) / 2;
    const int max_blocks  = 148 * 6;           // 6 blocks/SM at 128 thr
    const int grid        = total_pairs < max_blocks ? total_pairs : max_blocks;
    const int ppb_lo      = total_pairs / grid;
    const int extra       = total_pairs - ppb_lo * grid;

    sdf_kernel<<<grid, THREADS>>>(points, v, vn, sr, out,
                                  total_points, P, N, ppb_lo, extra);
}